// round 11
// baseline (speedup 1.0000x reference)
#include <cuda_runtime.h>
#include <math.h>

#define BB 32
#define HH 32
#define KVHH 8
#define DD 128
#define GG 4
#define BLK_SZ 16
#define MAX_BLOCKS 128
#define NSPLIT 8
#define NWARP 8
#define NTHREADS 256
#define NSLOT 16   // 2 half-warp slots per warp

// Scratch (allocation-free: __device__ globals)
__device__ float g_pacc[BB * KVHH * NSPLIT * GG * DD];  // 4 MB split partials
__device__ float g_pl[BB * KVHH * NSPLIT * GG];
__device__ float g_qrot[BB * HH * DD];    // RoPE'd q, scale folded
__device__ float g_krot[BB * KVHH * DD];  // RoPE'd new k

// ---------------- prep: RoPE q and new-k once (R7-proven) ----------------
__global__ __launch_bounds__(DD) void rope_prep_kernel(
    const float* __restrict__ query,
    const float* __restrict__ key,
    const int*   __restrict__ context_lens)
{
    const int b = blockIdx.x;
    const int h = blockIdx.y;   // 0..HH-1 q head, HH..HH+KVHH-1 k head
    const int d = threadIdx.x;

    const float pos = (float)context_lens[b];
    const int fi = d & 63;
    const float inv = exp2f(-(float)fi * 0.2076205092783674f);  // log2(10000)/64
    float s, c;
    sincosf(pos * inv, &s, &c);

    if (h < HH) {
        const float* base = query + ((long)b * HH + h) * DD;
        float x = base[d];
        float other = (d < 64) ? -base[d + 64] : base[d - 64];
        g_qrot[((long)b * HH + h) * DD + d] =
            (x * c + other * s) * 0.08838834764831845f;  // D^-0.5
    } else {
        const int kh = h - HH;
        const float* base = key + ((long)b * KVHH + kh) * DD;
        float x = base[d];
        float other = (d < 64) ? -base[d + 64] : base[d - 64];
        g_krot[((long)b * KVHH + kh) * DD + d] = x * c + other * s;
    }
}

// ------- 2-tokens-per-warp update: 16-lane halves, 4-level reduce -------
// Lane owns dims [gl*4, gl*4+4) and [64+gl*4, 64+gl*4+4) of its half's token.
__device__ __forceinline__ void upd2(
    const float4& kA, const float4& kB, const float4& vA, const float4& vB,
    const float4 qA[GG], const float4 qB[GG],
    float l[GG], float4 accA[GG], float4 accB[GG], bool valid)
{
    float sc[GG];
#pragma unroll
    for (int g = 0; g < GG; g++)
        sc[g] = kA.x * qA[g].x + kA.y * qA[g].y + kA.z * qA[g].z + kA.w * qA[g].w
              + kB.x * qB[g].x + kB.y * qB[g].y + kB.z * qB[g].z + kB.w * qB[g].w;
#pragma unroll
    for (int off = 8; off > 0; off >>= 1) {
#pragma unroll
        for (int g = 0; g < GG; g++)
            sc[g] += __shfl_xor_sync(0xffffffffu, sc[g], off);
    }
#pragma unroll
    for (int g = 0; g < GG; g++) {
        float p = valid ? __expf(sc[g]) : 0.f;
        l[g] += p;
        accA[g].x += p * vA.x; accA[g].y += p * vA.y;
        accA[g].z += p * vA.z; accA[g].w += p * vA.w;
        accB[g].x += p * vB.x; accB[g].y += p * vB.y;
        accB[g].z += p * vB.z; accB[g].w += p * vB.w;
    }
}

// ---------------- split flash-decode ----------------
__global__ __launch_bounds__(NTHREADS) void pa_split_kernel(
    const float* __restrict__ value,
    const float* __restrict__ k_cache,
    const float* __restrict__ v_cache,
    const int*   __restrict__ block_table,
    const int*   __restrict__ context_lens)
{
    const int split = blockIdx.x;
    const int kvh   = blockIdx.y;
    const int b     = blockIdx.z;
    const int tid   = threadIdx.x;
    const int lane  = tid & 31;
    const int w     = tid >> 5;
    const int gl    = lane & 15;
    const int half  = lane >> 4;
    const int dA    = gl * 4;        // first float4 dims
    const int dB    = dA + 64;       // second float4 dims

    const int ctx   = context_lens[b];
    const int chunk = (ctx + NSPLIT - 1) / NSPLIT;
    const int s0    = split * chunk;
    const int s1    = min(s0 + chunk, ctx);
    const int last  = ctx - 1;
    const int end   = min(s1, last);   // hot loop excludes in-flight token

    __shared__ int   btab[MAX_BLOCKS];
    __shared__ float wl[NSLOT][GG];
    __shared__ float wacc[NSLOT][GG][DD];

    for (int i = tid; i < MAX_BLOCKS; i += NTHREADS)
        btab[i] = block_table[b * MAX_BLOCKS + i];
    __syncthreads();

    float4 qA[GG], qB[GG];
#pragma unroll
    for (int g = 0; g < GG; g++) {
        const float* qp = &g_qrot[((long)b * HH + kvh * GG + g) * DD];
        qA[g] = *(const float4*)(qp + dA);
        qB[g] = *(const float4*)(qp + dB);
    }

    float l[GG];
    float4 accA[GG], accB[GG];
#pragma unroll
    for (int g = 0; g < GG; g++) {
        l[g] = 0.f;
        accA[g].x = accA[g].y = accA[g].z = accA[g].w = 0.f;
        accB[g].x = accB[g].y = accB[g].z = accB[g].w = 0.f;
    }

    const unsigned hbase = (unsigned)kvh * DD;
#define ROWOFF(t) (((unsigned)btab[(t) >> 4] * BLK_SZ + ((t) & 15)) * (KVHH * DD) + hbase)

    // lane's token per 16-token step: S + 2*w + half
    const int toff = 2 * w + half;
    int S = s0;
    // main: 2 steps (32 tokens), 8 LDG batched
    while (S + 32 <= end) {
        int t0 = S + toff, t1 = t0 + 16;
        unsigned r0 = ROWOFF(t0), r1 = ROWOFF(t1);
        float4 k0A = *(const float4*)(k_cache + r0 + dA);
        float4 k0B = *(const float4*)(k_cache + r0 + dB);
        float4 v0A = *(const float4*)(v_cache + r0 + dA);
        float4 v0B = *(const float4*)(v_cache + r0 + dB);
        float4 k1A = *(const float4*)(k_cache + r1 + dA);
        float4 k1B = *(const float4*)(k_cache + r1 + dB);
        float4 v1A = *(const float4*)(v_cache + r1 + dA);
        float4 v1B = *(const float4*)(v_cache + r1 + dB);
        upd2(k0A, k0B, v0A, v0B, qA, qB, l, accA, accB, true);
        upd2(k1A, k1B, v1A, v1B, qA, qB, l, accA, accB, true);
        S += 32;
    }
    while (S + 16 <= end) {
        int t = S + toff;
        unsigned r = ROWOFF(t);
        float4 kA = *(const float4*)(k_cache + r + dA);
        float4 kB = *(const float4*)(k_cache + r + dB);
        float4 vA = *(const float4*)(v_cache + r + dA);
        float4 vB = *(const float4*)(v_cache + r + dB);
        upd2(kA, kB, vA, vB, qA, qB, l, accA, accB, true);
        S += 16;
    }
    if (S < end) {
        int t = S + toff;
        bool valid = t < end;
        int tc = valid ? t : (end - 1);
        unsigned r = ROWOFF(tc);
        float4 kA = *(const float4*)(k_cache + r + dA);
        float4 kB = *(const float4*)(k_cache + r + dB);
        float4 vA = *(const float4*)(v_cache + r + dA);
        float4 vB = *(const float4*)(v_cache + r + dB);
        upd2(kA, kB, vA, vB, qA, qB, l, accA, accB, valid);
    }
#undef ROWOFF

    // in-flight token (RoPE'd new k from scratch, new v from input)
    if (last >= s0 && last < s1) {
        int o = (last - s0) & 15;
        if (w == (o >> 1)) {
            bool valid = (half == (o & 1));
            const float* kp = &g_krot[((long)b * KVHH + kvh) * DD];
            const float* vp = value + ((long)b * KVHH + kvh) * DD;
            float4 kA = *(const float4*)(kp + dA);
            float4 kB = *(const float4*)(kp + dB);
            float4 vA = *(const float4*)(vp + dA);
            float4 vB = *(const float4*)(vp + dB);
            upd2(kA, kB, vA, vB, qA, qB, l, accA, accB, valid);
        }
    }

    // stash per-half partials (16 slots)
    const int slot = 2 * w + half;
#pragma unroll
    for (int g = 0; g < GG; g++) {
        *(float4*)&wacc[slot][g][dA] = accA[g];
        *(float4*)&wacc[slot][g][dB] = accB[g];
    }
    if (gl == 0) {
#pragma unroll
        for (int g = 0; g < GG; g++) wl[slot][g] = l[g];
    }
    __syncthreads();

    const long pbase = ((long)(b * KVHH + kvh) * NSPLIT + split) * GG;
    for (int i = tid; i < GG * DD; i += NTHREADS) {
        int g = i >> 7, d = i & 127;
        float t = 0.f;
#pragma unroll
        for (int ss = 0; ss < NSLOT; ss++) t += wacc[ss][g][d];
        g_pacc[(pbase + g) * DD + d] = t;
    }
    if (tid < GG) {
        float L = 0.f;
#pragma unroll
        for (int ss = 0; ss < NSLOT; ss++) L += wl[ss][tid];
        g_pl[pbase + tid] = L;
    }
}

// ---------------- combine (plain sums) ----------------
__global__ __launch_bounds__(DD) void pa_combine_kernel(float* __restrict__ out) {
    const int idx = blockIdx.x;             // B*KVH*G
    const int g   = idx % GG;
    const int kvh = (idx / GG) % KVHH;
    const int b   = idx / (GG * KVHH);
    const int d   = threadIdx.x;

    const long base = ((long)(b * KVHH + kvh) * NSPLIT) * GG + g;
    float L = 0.f, o = 0.f;
#pragma unroll
    for (int s = 0; s < NSPLIT; s++) {
        L += g_pl[base + (long)s * GG];
        o += g_pacc[(base + (long)s * GG) * DD + d];
    }
    out[((long)b * HH + kvh * GG + g) * DD + d] = o / L;
}

extern "C" void kernel_launch(void* const* d_in, const int* in_sizes, int n_in,
                              void* d_out, int out_size) {
    const float* query  = (const float*)d_in[0];
    const float* key    = (const float*)d_in[1];
    const float* value  = (const float*)d_in[2];
    const float* k_cache = (const float*)d_in[3];
    const float* v_cache = (const float*)d_in[4];
    const int*   block_table  = (const int*)d_in[5];
    const int*   context_lens = (const int*)d_in[6];
    float* out = (float*)d_out;

    dim3 pgrid(BB, HH + KVHH);
    rope_prep_kernel<<<pgrid, DD>>>(query, key, context_lens);

    dim3 grid(NSPLIT, KVHH, BB);
    pa_split_kernel<<<grid, NTHREADS>>>(value, k_cache, v_cache,
                                        block_table, context_lens);
    pa_combine_kernel<<<BB * KVHH * GG, DD>>>(out);
}